// round 16
// baseline (speedup 1.0000x reference)
#include <cuda_runtime.h>

// SpatialTransformer: vol [B=2,192,192,192,1] fp32, affine [B,3,4] fp32.
// Warp = 32 consecutive w; UH=6 voxels/thread along h; two warp-uniform paths.
// NEW: temporal corner reuse along the h-unroll — when a lane's sample cell
// advances by exactly one h-row (idx == pidx + DIM, true for ~95% of lanes
// per step with a near-identity affine), the 4 lower-row corners are taken
// from the previous iteration's upper-row registers and their LDGs are
// predicated off, cutting L1 wavefronts ~30%.

#define DIM 192
#define SLAB (DIM * DIM)
#define BATCH 2
#define UH 6

__global__ __launch_bounds__(DIM) void st_warp_ru(
    const float* __restrict__ vol,
    const float* __restrict__ aff,
    float* __restrict__ out)
{
    const int w  = threadIdx.x;             // warp = 32 consecutive w
    const int h0 = blockIdx.x * UH;
    const int d  = blockIdx.y;
    const int b  = blockIdx.z;

    const float ctr  = (DIM - 1) * 0.5f;    // 95.5
    const float maxl = (float)(DIM - 1);    // 191

    // Affine: 3 broadcast LDG.128 (aff + b*12 floats is 16B-aligned).
    const float4* A4 = (const float4*)(aff + b * 12);
    const float4 r0 = __ldg(A4 + 0);
    const float4 r1 = __ldg(A4 + 1);
    const float4 r2 = __ldg(A4 + 2);
    const float a00 = r0.x, a01 = r0.y, a02 = r0.z, a03 = r0.w;
    const float a10 = r1.x, a11 = r1.y, a12 = r1.z, a13 = r1.w;
    const float a20 = r2.x, a21 = r2.y, a22 = r2.z, a23 = r2.w;

    const float cd = (float)d  - ctr;
    const float ch = (float)h0 - ctr;
    const float cw = (float)w  - ctr;

    // Sample location at j=0; along h it advances by (a01, a11, a21)/voxel.
    const float ld0 = fmaf(a00, cd, fmaf(a01, ch, fmaf(a02, cw, a03))) + ctr;
    const float lh0 = fmaf(a10, cd, fmaf(a11, ch, fmaf(a12, cw, a13))) + ctr;
    const float lw0 = fmaf(a20, cd, fmaf(a21, ch, fmaf(a22, cw, a23))) + ctr;

    const float* vb = vol + (size_t)b * (DIM * SLAB);
    float* ob = out + ((size_t)(b * DIM + d) * DIM + h0) * DIM + w;

    // ---- warp-uniform interior test for d,h dims (separable extrema) ----
    const int   wlo = w & ~31;
    const float chl = (float)h0 - ctr,  chh = (float)(h0 + UH - 1) - ctr;
    const float cwl = (float)wlo - ctr, cwh = (float)(wlo + 31) - ctr;

    const float bas_d = a00 * cd + a03 + ctr;
    const float lo_d  = bas_d + fminf(a01 * chl, a01 * chh) + fminf(a02 * cwl, a02 * cwh);
    const float hi_d  = bas_d + fmaxf(a01 * chl, a01 * chh) + fmaxf(a02 * cwl, a02 * cwh);
    const float bas_h = a10 * cd + a13 + ctr;
    const float lo_h  = bas_h + fminf(a11 * chl, a11 * chh) + fminf(a12 * cwl, a12 * cwh);
    const float hi_h  = bas_h + fmaxf(a11 * chl, a11 * chh) + fmaxf(a12 * cwl, a12 * cwh);

    // 0.5 guard >> fp discrepancy (~1e-4) between extrema and fma chains.
    const bool fast = (lo_d > 0.5f) & (hi_d < 190.5f) &
                      (lo_h > 0.5f) & (hi_h < 190.5f);

    if (fast) {
        // ---- fast path: d,h interior; w general; temporal corner reuse ----
        int   pidx = -1000000;              // never matches at j=0
        float pv010 = 0.f, pv011 = 0.f, pv110 = 0.f, pv111 = 0.f;

#pragma unroll
        for (int j = 0; j < UH; j++) {
            const float fj = (float)j;
            const float ldv = fmaf(a01, fj, ld0);
            const float lhv = fmaf(a11, fj, lh0);
            const float lwv = fmaf(a21, fj, lw0);

            const int   id = (int)ldv;  const float td = ldv - (float)id;
            const int   ih = (int)lhv;  const float th = lhv - (float)ih;

            const float sw = fminf(fmaxf(lwv, 0.f), maxl);
            const int   iw = (int)sw;
            const float tw = sw - (float)iw;
            const int   ow = (iw < DIM - 1) ? 1 : 0;

            const int idx = id * SLAB + ih * DIM + iw;
            const float* p  = vb + idx;
            const float* p2 = p + ow;

            // Lower h-row corners: reuse previous upper row when the cell
            // advanced by exactly one h-row (single index compare proves
            // id/ih/iw relation; ow follows from iw). Predicated LDGs: lanes
            // that reuse generate no L1 sectors.
            const bool ru = (idx == pidx + DIM);
            const float v000 = ru ? pv010 : __ldg(p);
            const float v001 = ru ? pv011 : __ldg(p2);
            const float v100 = ru ? pv110 : __ldg(p  + SLAB);
            const float v101 = ru ? pv111 : __ldg(p2 + SLAB);

            // Upper h-row corners: always loaded, cached for next iteration.
            const float v010 = __ldg(p  + DIM);
            const float v011 = __ldg(p2 + DIM);
            const float v110 = __ldg(p  + SLAB + DIM);
            const float v111 = __ldg(p2 + SLAB + DIM);

            const float p00 = fmaf(tw, v001 - v000, v000);
            const float p01 = fmaf(tw, v011 - v010, v010);
            const float p10 = fmaf(tw, v101 - v100, v100);
            const float p11 = fmaf(tw, v111 - v110, v110);
            const float q0  = fmaf(th, p01 - p00, p00);
            const float q1  = fmaf(th, p11 - p10, p10);

            ob[j * DIM] = fmaf(td, q1 - q0, q0);

            pidx = idx;
            pv010 = v010; pv011 = v011; pv110 = v110; pv111 = v111;
        }
    } else {
        // ---- general path: exact reference clamp semantics every dim ----
#pragma unroll
        for (int j = 0; j < UH; j++) {
            const float fj = (float)j;
            const float ldv = fmaf(a01, fj, ld0);
            const float lhv = fmaf(a11, fj, lh0);
            const float lwv = fmaf(a21, fj, lw0);

            const float sd = fminf(fmaxf(ldv, 0.f), maxl);
            const int   id = (int)sd;
            const float td = sd - (float)id;
            const int   od = (id < DIM - 1) ? SLAB : 0;

            const float sh = fminf(fmaxf(lhv, 0.f), maxl);
            const int   ih = (int)sh;
            const float th = sh - (float)ih;
            const int   oh = (ih < DIM - 1) ? DIM : 0;

            const float sw = fminf(fmaxf(lwv, 0.f), maxl);
            const int   iw = (int)sw;
            const float tw = sw - (float)iw;
            const int   ow = (iw < DIM - 1) ? 1 : 0;

            const float* p = vb + (id * SLAB + ih * DIM + iw);

            const float v000 = __ldg(p);
            const float v001 = __ldg(p + ow);
            const float v010 = __ldg(p + oh);
            const float v011 = __ldg(p + oh + ow);
            const float* q = p + od;
            const float v100 = __ldg(q);
            const float v101 = __ldg(q + ow);
            const float v110 = __ldg(q + oh);
            const float v111 = __ldg(q + oh + ow);

            const float p00 = fmaf(tw, v001 - v000, v000);
            const float p01 = fmaf(tw, v011 - v010, v010);
            const float p10 = fmaf(tw, v101 - v100, v100);
            const float p11 = fmaf(tw, v111 - v110, v110);
            const float q0  = fmaf(th, p01 - p00, p00);
            const float q1  = fmaf(th, p11 - p10, p10);

            ob[j * DIM] = fmaf(td, q1 - q0, q0);
        }
    }
}

extern "C" void kernel_launch(void* const* d_in, const int* in_sizes, int n_in,
                              void* d_out, int out_size)
{
    const float* vol = (const float*)d_in[0];
    const float* aff = (const float*)d_in[1];
    float* out = (float*)d_out;

    dim3 grid(DIM / UH, DIM, BATCH);   // (32, 192, 2)
    dim3 block(DIM);                   // 192 threads, warp = 32 consecutive w
    st_warp_ru<<<grid, block>>>(vol, aff, out);
}

// round 17
// speedup vs baseline: 1.0775x; 1.0775x over previous
#include <cuda_runtime.h>

// SpatialTransformer: vol [B=2,192,192,192,1] fp32, affine [B,3,4] fp32.
// R9 body (best kernel: warp = 32 consecutive w, UH=6, two warp-uniform
// paths, float4 broadcast affine) + software-pipelined j-PAIRS in the fast
// path: both iterations' 16 gathers are issued back-to-back before either
// blend tree, doubling per-warp MLP to hide L2-hit + L1tex-queue latency.

#define DIM 192
#define SLAB (DIM * DIM)
#define BATCH 2
#define UH 6

__global__ __launch_bounds__(DIM) void st_warp_p2(
    const float* __restrict__ vol,
    const float* __restrict__ aff,
    float* __restrict__ out)
{
    const int w  = threadIdx.x;             // warp = 32 consecutive w
    const int h0 = blockIdx.x * UH;
    const int d  = blockIdx.y;
    const int b  = blockIdx.z;

    const float ctr  = (DIM - 1) * 0.5f;    // 95.5
    const float maxl = (float)(DIM - 1);    // 191

    // Affine: 3 broadcast LDG.128 (aff + b*12 floats is 16B-aligned).
    const float4* A4 = (const float4*)(aff + b * 12);
    const float4 r0 = __ldg(A4 + 0);
    const float4 r1 = __ldg(A4 + 1);
    const float4 r2 = __ldg(A4 + 2);
    const float a00 = r0.x, a01 = r0.y, a02 = r0.z, a03 = r0.w;
    const float a10 = r1.x, a11 = r1.y, a12 = r1.z, a13 = r1.w;
    const float a20 = r2.x, a21 = r2.y, a22 = r2.z, a23 = r2.w;

    const float cd = (float)d  - ctr;
    const float ch = (float)h0 - ctr;
    const float cw = (float)w  - ctr;

    // Sample location at j=0; along h it advances by (a01, a11, a21)/voxel.
    const float ld0 = fmaf(a00, cd, fmaf(a01, ch, fmaf(a02, cw, a03))) + ctr;
    const float lh0 = fmaf(a10, cd, fmaf(a11, ch, fmaf(a12, cw, a13))) + ctr;
    const float lw0 = fmaf(a20, cd, fmaf(a21, ch, fmaf(a22, cw, a23))) + ctr;

    const float* vb = vol + (size_t)b * (DIM * SLAB);
    float* ob = out + ((size_t)(b * DIM + d) * DIM + h0) * DIM + w;

    // ---- warp-uniform interior test for d,h dims (separable extrema) ----
    const int   wlo = w & ~31;
    const float chl = (float)h0 - ctr,  chh = (float)(h0 + UH - 1) - ctr;
    const float cwl = (float)wlo - ctr, cwh = (float)(wlo + 31) - ctr;

    const float bas_d = a00 * cd + a03 + ctr;
    const float lo_d  = bas_d + fminf(a01 * chl, a01 * chh) + fminf(a02 * cwl, a02 * cwh);
    const float hi_d  = bas_d + fmaxf(a01 * chl, a01 * chh) + fmaxf(a02 * cwl, a02 * cwh);
    const float bas_h = a10 * cd + a13 + ctr;
    const float lo_h  = bas_h + fminf(a11 * chl, a11 * chh) + fminf(a12 * cwl, a12 * cwh);
    const float hi_h  = bas_h + fmaxf(a11 * chl, a11 * chh) + fmaxf(a12 * cwl, a12 * cwh);

    // 0.5 guard >> fp discrepancy (~1e-4) between extrema and fma chains.
    const bool fast = (lo_d > 0.5f) & (hi_d < 190.5f) &
                      (lo_h > 0.5f) & (hi_h < 190.5f);

    if (fast) {
        // ---- fast path: d,h interior; w general; j processed in PAIRS ----
#pragma unroll
        for (int jj = 0; jj < UH; jj += 2) {
            // --- addresses for j = jj ---
            const float fa = (float)jj;
            const float ldA = fmaf(a01, fa, ld0);
            const float lhA = fmaf(a11, fa, lh0);
            const float lwA = fmaf(a21, fa, lw0);
            const int   idA = (int)ldA;  const float tdA = ldA - (float)idA;
            const int   ihA = (int)lhA;  const float thA = lhA - (float)ihA;
            const float swA = fminf(fmaxf(lwA, 0.f), maxl);
            const int   iwA = (int)swA;
            const float twA = swA - (float)iwA;
            const int   owA = (iwA < DIM - 1) ? 1 : 0;
            const float* pA  = vb + (idA * SLAB + ihA * DIM + iwA);
            const float* pA2 = pA + owA;

            // --- addresses for j = jj+1 ---
            const float fb = (float)(jj + 1);
            const float ldB = fmaf(a01, fb, ld0);
            const float lhB = fmaf(a11, fb, lh0);
            const float lwB = fmaf(a21, fb, lw0);
            const int   idB = (int)ldB;  const float tdB = ldB - (float)idB;
            const int   ihB = (int)lhB;  const float thB = lhB - (float)ihB;
            const float swB = fminf(fmaxf(lwB, 0.f), maxl);
            const int   iwB = (int)swB;
            const float twB = swB - (float)iwB;
            const int   owB = (iwB < DIM - 1) ? 1 : 0;
            const float* pB  = vb + (idB * SLAB + ihB * DIM + iwB);
            const float* pB2 = pB + owB;

            // --- issue all 16 gathers before any blend (max MLP) ---
            const float a000 = __ldg(pA);
            const float a001 = __ldg(pA2);
            const float a010 = __ldg(pA  + DIM);
            const float a011 = __ldg(pA2 + DIM);
            const float a100 = __ldg(pA  + SLAB);
            const float a101 = __ldg(pA2 + SLAB);
            const float a110 = __ldg(pA  + SLAB + DIM);
            const float a111 = __ldg(pA2 + SLAB + DIM);

            const float b000 = __ldg(pB);
            const float b001 = __ldg(pB2);
            const float b010 = __ldg(pB  + DIM);
            const float b011 = __ldg(pB2 + DIM);
            const float b100 = __ldg(pB  + SLAB);
            const float b101 = __ldg(pB2 + SLAB);
            const float b110 = __ldg(pB  + SLAB + DIM);
            const float b111 = __ldg(pB2 + SLAB + DIM);

            // --- blend j = jj ---
            {
                const float p00 = fmaf(twA, a001 - a000, a000);
                const float p01 = fmaf(twA, a011 - a010, a010);
                const float p10 = fmaf(twA, a101 - a100, a100);
                const float p11 = fmaf(twA, a111 - a110, a110);
                const float q0  = fmaf(thA, p01 - p00, p00);
                const float q1  = fmaf(thA, p11 - p10, p10);
                ob[jj * DIM] = fmaf(tdA, q1 - q0, q0);
            }
            // --- blend j = jj+1 ---
            {
                const float p00 = fmaf(twB, b001 - b000, b000);
                const float p01 = fmaf(twB, b011 - b010, b010);
                const float p10 = fmaf(twB, b101 - b100, b100);
                const float p11 = fmaf(twB, b111 - b110, b110);
                const float q0  = fmaf(thB, p01 - p00, p00);
                const float q1  = fmaf(thB, p11 - p10, p10);
                ob[(jj + 1) * DIM] = fmaf(tdB, q1 - q0, q0);
            }
        }
    } else {
        // ---- general path: exact reference clamp semantics every dim ----
#pragma unroll
        for (int j = 0; j < UH; j++) {
            const float fj = (float)j;
            const float ldv = fmaf(a01, fj, ld0);
            const float lhv = fmaf(a11, fj, lh0);
            const float lwv = fmaf(a21, fj, lw0);

            const float sd = fminf(fmaxf(ldv, 0.f), maxl);
            const int   id = (int)sd;
            const float td = sd - (float)id;
            const int   od = (id < DIM - 1) ? SLAB : 0;

            const float sh = fminf(fmaxf(lhv, 0.f), maxl);
            const int   ih = (int)sh;
            const float th = sh - (float)ih;
            const int   oh = (ih < DIM - 1) ? DIM : 0;

            const float sw = fminf(fmaxf(lwv, 0.f), maxl);
            const int   iw = (int)sw;
            const float tw = sw - (float)iw;
            const int   ow = (iw < DIM - 1) ? 1 : 0;

            const float* p = vb + (id * SLAB + ih * DIM + iw);

            const float v000 = __ldg(p);
            const float v001 = __ldg(p + ow);
            const float v010 = __ldg(p + oh);
            const float v011 = __ldg(p + oh + ow);
            const float* q = p + od;
            const float v100 = __ldg(q);
            const float v101 = __ldg(q + ow);
            const float v110 = __ldg(q + oh);
            const float v111 = __ldg(q + oh + ow);

            const float p00 = fmaf(tw, v001 - v000, v000);
            const float p01 = fmaf(tw, v011 - v010, v010);
            const float p10 = fmaf(tw, v101 - v100, v100);
            const float p11 = fmaf(tw, v111 - v110, v110);
            const float q0  = fmaf(th, p01 - p00, p00);
            const float q1  = fmaf(th, p11 - p10, p10);

            ob[j * DIM] = fmaf(td, q1 - q0, q0);
        }
    }
}

extern "C" void kernel_launch(void* const* d_in, const int* in_sizes, int n_in,
                              void* d_out, int out_size)
{
    const float* vol = (const float*)d_in[0];
    const float* aff = (const float*)d_in[1];
    float* out = (float*)d_out;

    dim3 grid(DIM / UH, DIM, BATCH);   // (32, 192, 2)
    dim3 block(DIM);                   // 192 threads, warp = 32 consecutive w
    st_warp_p2<<<grid, block>>>(vol, aff, out);
}